// round 2
// baseline (speedup 1.0000x reference)
#include <cuda_runtime.h>
#include <cuda_fp16.h>
#include <cstdint>
#include <cstddef>

// ---------------------------------------------------------------------------
// ActorUpAction fused kernel: fp16 mma.sync, fully fused in SMEM.
//   action: tanh([x,m]) -> 256x256 relu -> 256x256 relu -> dot(256) -> tanh
//   msg:    l2n(x@fc1[64x128]) -> tanh([hx,m]) -> tanh(fc2[64x192]) -> l2n(fc3[32x64])
// Output layout: msg_up [B,32] fp32 followed by action [B] fp32.
// ---------------------------------------------------------------------------

#define SA 264   // stride (halves) for 256-wide tiles (K=256 + 8 pad)
#define SZ 200   // stride for Z / fc2 weights (K=192 + 8)
#define SX 136   // stride for raw-x / fc1 weights (K=128 + 8)
#define SZ2 72   // stride for Z2 / fc3 weights (K=64 + 8)
#define SS 68    // float stride, fc1 staging
#define SS2 36   // float stride, fc3 staging

#define SMEM_HALVES (2*128*264 + 64*264 + 128*136)
#define SMEM_BYTES  (SMEM_HALVES*2)   // 203776 bytes

__device__ __half g_w1[256*256];
__device__ __half g_w2[256*256];
__device__ __half g_w3[256];
__device__ __half g_f1[64*128];
__device__ __half g_f2[64*192];
__device__ __half g_f3[32*64];

__global__ void cvtw_kernel(const float* __restrict__ w1, const float* __restrict__ w2,
                            const float* __restrict__ w3, const float* __restrict__ f1,
                            const float* __restrict__ f2, const float* __restrict__ f3) {
    int i = blockIdx.x * blockDim.x + threadIdx.x;   // grid covers 65536
    g_w1[i] = __float2half_rn(w1[i]);
    g_w2[i] = __float2half_rn(w2[i]);
    if (i < 256)   g_w3[i] = __float2half_rn(w3[i]);
    if (i < 8192)  g_f1[i] = __float2half_rn(f1[i]);
    if (i < 12288) g_f2[i] = __float2half_rn(f2[i]);
    if (i < 2048)  g_f3[i] = __float2half_rn(f3[i]);
}

static __device__ __forceinline__ unsigned su(const void* p) {
    return (unsigned)__cvta_generic_to_shared(p);
}
static __device__ __forceinline__ void ldm_x4(uint32_t* r, unsigned a) {
    asm volatile("ldmatrix.sync.aligned.m8n8.x4.shared.b16 {%0,%1,%2,%3}, [%4];"
                 : "=r"(r[0]), "=r"(r[1]), "=r"(r[2]), "=r"(r[3]) : "r"(a));
}
static __device__ __forceinline__ void ldm_x2(uint32_t* r, unsigned a) {
    asm volatile("ldmatrix.sync.aligned.m8n8.x2.shared.b16 {%0,%1}, [%2];"
                 : "=r"(r[0]), "=r"(r[1]) : "r"(a));
}
static __device__ __forceinline__ void mma16816(float* c, const uint32_t* a, const uint32_t* b) {
    asm volatile("mma.sync.aligned.m16n8k16.row.col.f32.f16.f16.f32 "
                 "{%0,%1,%2,%3}, {%4,%5,%6,%7}, {%8,%9}, {%0,%1,%2,%3};"
                 : "+f"(c[0]), "+f"(c[1]), "+f"(c[2]), "+f"(c[3])
                 : "r"(a[0]), "r"(a[1]), "r"(a[2]), "r"(a[3]), "r"(b[0]), "r"(b[1]));
}

// fast tanh: exp2 MUFU (~2ulp) rational form
static __device__ __forceinline__ float ft(float v) {
    v = fminf(8.0f, fmaxf(-8.0f, v));
    float e;
    asm("ex2.approx.f32 %0, %1;" : "=f"(e) : "f"(v * 2.8853900817779268f)); // 2*log2(e)
    return __fdividef(e - 1.0f, e + 1.0f);
}

// Warp GEMM: 32 rows x (NF*8) cols, K contraction, fp32 accum.
// A: row-major [rows,K] fp16 smem, LDA halves. W: row-major [cols,K], LDW halves.
template <int NF, int K, int LDA, int LDW>
static __device__ __forceinline__ void warp_gemm(const __half* Aw, const __half* Ww,
                                                 float acc[2][NF][4], int lane) {
    unsigned aB = su(Aw + (lane & 15) * LDA + (lane >> 4) * 8);
    unsigned bB = su(Ww + (lane & 7) * LDW + ((lane >> 3) & 1) * 8);
#pragma unroll
    for (int k0 = 0; k0 < K; k0 += 16) {
        uint32_t a0[4], a1[4];
        ldm_x4(a0, aB + 2 * k0);
        ldm_x4(a1, aB + 32 * LDA + 2 * k0);   // +16 rows (byte addr)
#pragma unroll
        for (int ni = 0; ni < NF; ni++) {
            uint32_t b[2];
            ldm_x2(b, bB + ni * 16 * LDW + 2 * k0);   // +8 cols per frag (byte addr)
            mma16816(acc[0][ni], a0, b);
            mma16816(acc[1][ni], a1, b);
        }
    }
}

#define ZERO_ACC(A, NFv)                                            \
    _Pragma("unroll") for (int _a = 0; _a < 2; _a++)                \
    _Pragma("unroll") for (int _b = 0; _b < NFv; _b++)              \
    _Pragma("unroll") for (int _c = 0; _c < 4; _c++) A[_a][_b][_c] = 0.f;

__global__ void __launch_bounds__(256, 1)
actor_kernel(const float* __restrict__ gx, const float* __restrict__ gm,
             const float* __restrict__ fc1_b, const float* __restrict__ fc2_b,
             const float* __restrict__ fc3_b, const float* __restrict__ ab_b1,
             const float* __restrict__ ab_b2, const float* __restrict__ ab_b3,
             float* __restrict__ out, int nrows) {
    extern __shared__ __half sm[];
    __half* bufA = sm;                             // [128][264] tanh(xm); later h2
    __half* bufH = sm + 128 * 264;                 // [128][264] h1; earlier Z [128][200]
    __half* bufW = sm + 2 * 128 * 264;             // 16896 halves, streamed weights
    __half* bufX = sm + 2 * 128 * 264 + 64 * 264;  // [128][136] raw x; aliases S, Z2
    float*  bufS = (float*)bufX;                   // [128][68]
    float*  bufS2 = (float*)(bufW + 4096);         // [128][36] (past fc3 weights)

    const int tid = threadIdx.x;
    const int lane = tid & 31;
    const int wid = tid >> 5;
    const int wm = wid & 3;
    const int wn = wid >> 2;
    const int rin = lane >> 2;
    const int cin = (lane & 3) * 2;
    const int row0 = blockIdx.x * 128;

    // ---- stage inputs: raw x (fp16) + tanh(x), tanh(m) (fp16) ----
    const float4* x4 = (const float4*)(gx + (size_t)row0 * 128);
    const float4* m4 = (const float4*)(gm + (size_t)row0 * 128);
#pragma unroll
    for (int it = 0; it < 16; it++) {
        int i = tid + it * 256;
        int r = i >> 5, c = i & 31;   // 32 float4 per row
        float4 v = x4[i];
        __half2* xd = (__half2*)(bufX + r * SX + c * 4);
        xd[0] = __floats2half2_rn(v.x, v.y);
        xd[1] = __floats2half2_rn(v.z, v.w);
        __half2* ad = (__half2*)(bufA + r * SA + c * 4);
        ad[0] = __floats2half2_rn(ft(v.x), ft(v.y));
        ad[1] = __floats2half2_rn(ft(v.z), ft(v.w));
        float4 w = m4[i];
        __half2* md = (__half2*)(bufA + r * SA + 128 + c * 4);
        md[0] = __floats2half2_rn(ft(w.x), ft(w.y));
        md[1] = __floats2half2_rn(ft(w.z), ft(w.w));
    }
    {   // fc1 weights [64][128] -> bufW (stride SX)
        const uint4* s = (const uint4*)g_f1;
        for (int i = tid; i < 1024; i += 256) {
            int r = i >> 4, c = i & 15;
            *(uint4*)(bufW + r * SX + c * 8) = s[i];
        }
    }
    __syncthreads();

    // ---- fc1: [128,64] = x @ fc1^T ----
    float acc[2][4][4];
    ZERO_ACC(acc, 4)
    warp_gemm<4, 128, SX, SX>(bufX + wm * 32 * SX, bufW + wn * 32 * SX, acc, lane);
    __syncthreads();   // all reads of bufX done before S (aliased) is written
#pragma unroll
    for (int mi = 0; mi < 2; mi++)
#pragma unroll
        for (int ni = 0; ni < 4; ni++) {
            int row = wm * 32 + mi * 16 + rin;
            int col = wn * 32 + ni * 8 + cin;
            bufS[row * SS + col]           = acc[mi][ni][0] + fc1_b[col];
            bufS[row * SS + col + 1]       = acc[mi][ni][1] + fc1_b[col + 1];
            bufS[(row + 8) * SS + col]     = acc[mi][ni][2] + fc1_b[col];
            bufS[(row + 8) * SS + col + 1] = acc[mi][ni][3] + fc1_b[col + 1];
        }
    __syncthreads();

    // ---- l2norm + tanh -> Z[:,0:64]; copy tanh(m) -> Z[:,64:192] ----
    {
        int r = tid >> 1, h = tid & 1;
        const float* Sr = bufS + r * SS + h * 32;
        float s = 0.f;
#pragma unroll
        for (int c = 0; c < 32; c++) s += Sr[c] * Sr[c];
        s += __shfl_xor_sync(0xffffffffu, s, 1);
        float inv = 1.0f / fmaxf(sqrtf(s), 1e-12f);
#pragma unroll
        for (int c = 0; c < 32; c += 2)
            *(__half2*)(bufH + r * SZ + h * 32 + c) =
                __floats2half2_rn(ft(Sr[c] * inv), ft(Sr[c + 1] * inv));
    }
#pragma unroll
    for (int it = 0; it < 16; it++) {
        int i = tid + it * 256;
        int r = i >> 5, c = i & 31;
        *(uint2*)(bufH + r * SZ + 64 + c * 4) = *(const uint2*)(bufA + r * SA + 128 + c * 4);
    }
    {   // fc2 weights [64][192] -> bufW (stride SZ)
        const uint4* s = (const uint4*)g_f2;
        for (int i = tid; i < 1536; i += 256) {
            int r = i / 24, c = i % 24;
            *(uint4*)(bufW + r * SZ + c * 8) = s[i];
        }
    }
    __syncthreads();

    // ---- fc2: tanh(Z @ fc2^T) -> Z2 (bufX region, stride SZ2) ----
    ZERO_ACC(acc, 4)
    warp_gemm<4, 192, SZ, SZ>(bufH + wm * 32 * SZ, bufW + wn * 32 * SZ, acc, lane);
#pragma unroll
    for (int mi = 0; mi < 2; mi++)
#pragma unroll
        for (int ni = 0; ni < 4; ni++) {
            int row = wm * 32 + mi * 16 + rin;
            int col = wn * 32 + ni * 8 + cin;
            *(__half2*)(bufX + row * SZ2 + col) = __floats2half2_rn(
                ft(acc[mi][ni][0] + fc2_b[col]), ft(acc[mi][ni][1] + fc2_b[col + 1]));
            *(__half2*)(bufX + (row + 8) * SZ2 + col) = __floats2half2_rn(
                ft(acc[mi][ni][2] + fc2_b[col]), ft(acc[mi][ni][3] + fc2_b[col + 1]));
        }
    __syncthreads();
    {   // fc3 weights [32][64] -> bufW (stride SZ2)
        const uint4* s = (const uint4*)g_f3;
        if (tid < 256) {
            int r = tid >> 3, c = tid & 7;
            *(uint4*)(bufW + r * SZ2 + c * 8) = s[tid];
        }
    }
    __syncthreads();

    // ---- fc3: [128,32] = Z2 @ fc3^T -> S2, then l2norm -> msg_up ----
    {
        float acc3[2][2][4];
        ZERO_ACC(acc3, 2)
        warp_gemm<2, 64, SZ2, SZ2>(bufX + wm * 32 * SZ2, bufW + wn * 16 * SZ2, acc3, lane);
#pragma unroll
        for (int mi = 0; mi < 2; mi++)
#pragma unroll
            for (int ni = 0; ni < 2; ni++) {
                int row = wm * 32 + mi * 16 + rin;
                int col = wn * 16 + ni * 8 + cin;
                bufS2[row * SS2 + col]           = acc3[mi][ni][0] + fc3_b[col];
                bufS2[row * SS2 + col + 1]       = acc3[mi][ni][1] + fc3_b[col + 1];
                bufS2[(row + 8) * SS2 + col]     = acc3[mi][ni][2] + fc3_b[col];
                bufS2[(row + 8) * SS2 + col + 1] = acc3[mi][ni][3] + fc3_b[col + 1];
            }
    }
    __syncthreads();
    {
        int r = tid >> 1, h = tid & 1;
        const float* Sr = bufS2 + r * SS2 + h * 16;
        float s = 0.f;
#pragma unroll
        for (int c = 0; c < 16; c++) s += Sr[c] * Sr[c];
        s += __shfl_xor_sync(0xffffffffu, s, 1);
        float inv = 1.0f / fmaxf(sqrtf(s), 1e-12f);
        float* od = out + (size_t)(row0 + r) * 32 + h * 16;
#pragma unroll
        for (int c = 0; c < 16; c++) od[c] = Sr[c] * inv;
    }

    // ---- action layer 1: h1 = relu(xm_t @ W1^T) -> bufH, 4 chunks of 64 cols ----
#pragma unroll 1
    for (int ch = 0; ch < 4; ch++) {
        __syncthreads();   // prior readers of bufW done
        {
            const uint4* s = (const uint4*)(g_w1 + ch * 64 * 256);
            for (int i = tid; i < 2048; i += 256) {
                int r = i >> 5, c = i & 31;
                *(uint4*)(bufW + r * SA + c * 8) = s[i];
            }
        }
        __syncthreads();
        ZERO_ACC(acc, 4)
        warp_gemm<4, 256, SA, SA>(bufA + wm * 32 * SA, bufW + wn * 32 * SA, acc, lane);
#pragma unroll
        for (int mi = 0; mi < 2; mi++)
#pragma unroll
            for (int ni = 0; ni < 4; ni++) {
                int row = wm * 32 + mi * 16 + rin;
                int colg = ch * 64 + wn * 32 + ni * 8 + cin;
                float b0 = ab_b1[colg], b1v = ab_b1[colg + 1];
                *(__half2*)(bufH + row * SA + colg) = __floats2half2_rn(
                    fmaxf(acc[mi][ni][0] + b0, 0.f), fmaxf(acc[mi][ni][1] + b1v, 0.f));
                *(__half2*)(bufH + (row + 8) * SA + colg) = __floats2half2_rn(
                    fmaxf(acc[mi][ni][2] + b0, 0.f), fmaxf(acc[mi][ni][3] + b1v, 0.f));
            }
    }

    // ---- action layer 2: h2 = relu(h1 @ W2^T) -> bufA, 4 chunks ----
#pragma unroll 1
    for (int ch = 0; ch < 4; ch++) {
        __syncthreads();   // prior gemm reads of bufW + layer1 writeback done
        {
            const uint4* s = (const uint4*)(g_w2 + ch * 64 * 256);
            for (int i = tid; i < 2048; i += 256) {
                int r = i >> 5, c = i & 31;
                *(uint4*)(bufW + r * SA + c * 8) = s[i];
            }
        }
        __syncthreads();
        ZERO_ACC(acc, 4)
        warp_gemm<4, 256, SA, SA>(bufH + wm * 32 * SA, bufW + wn * 32 * SA, acc, lane);
#pragma unroll
        for (int mi = 0; mi < 2; mi++)
#pragma unroll
            for (int ni = 0; ni < 4; ni++) {
                int row = wm * 32 + mi * 16 + rin;
                int colg = ch * 64 + wn * 32 + ni * 8 + cin;
                float b0 = ab_b2[colg], b1v = ab_b2[colg + 1];
                *(__half2*)(bufA + row * SA + colg) = __floats2half2_rn(
                    fmaxf(acc[mi][ni][0] + b0, 0.f), fmaxf(acc[mi][ni][1] + b1v, 0.f));
                *(__half2*)(bufA + (row + 8) * SA + colg) = __floats2half2_rn(
                    fmaxf(acc[mi][ni][2] + b0, 0.f), fmaxf(acc[mi][ni][3] + b1v, 0.f));
            }
    }
    __syncthreads();

    // ---- final: action = tanh(h2 . w3 + b3) ----
    {
        int r = tid >> 1, h = tid & 1;
        const __half2* hv = (const __half2*)(bufA + r * SA + h * 128);
        const __half2* wv = (const __half2*)(g_w3 + h * 128);
        float s = 0.f;
#pragma unroll
        for (int c = 0; c < 64; c++) {
            float2 a2 = __half22float2(hv[c]);
            float2 w2 = __half22float2(wv[c]);
            s += a2.x * w2.x + a2.y * w2.y;
        }
        s += __shfl_xor_sync(0xffffffffu, s, 1);
        if (h == 0)
            out[(size_t)nrows * 32 + row0 + r] = ft(s + ab_b3[0]);
    }
}

extern "C" void kernel_launch(void* const* d_in, const int* in_sizes, int n_in,
                              void* d_out, int out_size) {
    const float* x     = (const float*)d_in[0];
    const float* m     = (const float*)d_in[1];
    const float* fc1_w = (const float*)d_in[2];
    const float* fc1_b = (const float*)d_in[3];
    const float* fc2_w = (const float*)d_in[4];
    const float* fc2_b = (const float*)d_in[5];
    const float* fc3_w = (const float*)d_in[6];
    const float* fc3_b = (const float*)d_in[7];
    const float* ab_w1 = (const float*)d_in[8];
    const float* ab_b1 = (const float*)d_in[9];
    const float* ab_w2 = (const float*)d_in[10];
    const float* ab_b2 = (const float*)d_in[11];
    const float* ab_w3 = (const float*)d_in[12];
    const float* ab_b3 = (const float*)d_in[13];
    float* out = (float*)d_out;
    int nrows = in_sizes[0] / 128;

    static bool attr_done = false;
    if (!attr_done) {
        cudaFuncSetAttribute(actor_kernel,
                             cudaFuncAttributeMaxDynamicSharedMemorySize, SMEM_BYTES);
        attr_done = true;
    }

    cvtw_kernel<<<256, 256>>>(ab_w1, ab_w2, ab_w3, fc1_w, fc2_w, fc3_w);
    actor_kernel<<<nrows / 128, 256, SMEM_BYTES>>>(
        x, m, fc1_b, fc2_b, fc3_b, ab_b1, ab_b2, ab_b3, out, nrows);
}

// round 4
// speedup vs baseline: 1.1775x; 1.1775x over previous
#include <cuda_runtime.h>
#include <cuda_fp16.h>
#include <cstdint>
#include <cstddef>

// ---------------------------------------------------------------------------
// ActorUpAction fused kernel v2b: fp16 mma.sync, 512 threads (16 warps),
// B-operand ldmatrix.x4, register-resident l2norm. (v2 + staging-count fixes)
//   action: tanh([x,m]) -> 256x256 relu -> 256x256 relu -> dot(256) -> tanh
//   msg:    l2n(x@fc1[64x128]) -> tanh([hx,m]) -> tanh(fc2[64x192]) -> l2n(fc3[32x64])
// Output: msg_up [B,32] fp32 then action [B] fp32.
// ---------------------------------------------------------------------------

#define SA 264   // stride (halves), 256-wide tiles (K=256 + 8 pad)
#define SZ 200   // stride, Z / fc2 weights (K=192 + 8)
#define SX 136   // stride, raw-x / fc1 weights (K=128 + 8)
#define SZ2 72   // stride, Z2 / fc3 weights (K=64 + 8)

// bufW internal offsets (halves)
#define OFF_F1W 0        // 64 x SX  = 8704
#define OFF_F2W 8704     // 64 x SZ  = 12800 -> ends 21504
#define OFF_F3W 21504    // 32 x SZ2 = 2304  -> ends 23808
#define OFF_PART 23808   // 512 floats = 1024 halves -> ends 24832
#define OFF_Z2 0         // 128 x SZ2 = 9216 (F1W dead, F2W-head protected by sync)

#define SMEM_HALVES (3*128*264)
#define SMEM_BYTES  (SMEM_HALVES*2)   // 202752 bytes

__device__ __half g_w1[256*256];
__device__ __half g_w2[256*256];
__device__ __half g_w3[256];
__device__ __half g_f1[64*128];
__device__ __half g_f2[64*192];
__device__ __half g_f3[32*64];

__global__ void cvtw_kernel(const float* __restrict__ w1, const float* __restrict__ w2,
                            const float* __restrict__ w3, const float* __restrict__ f1,
                            const float* __restrict__ f2, const float* __restrict__ f3) {
    int i = blockIdx.x * blockDim.x + threadIdx.x;   // grid covers 65536
    g_w1[i] = __float2half_rn(w1[i]);
    g_w2[i] = __float2half_rn(w2[i]);
    if (i < 256)   g_w3[i] = __float2half_rn(w3[i]);
    if (i < 8192)  g_f1[i] = __float2half_rn(f1[i]);
    if (i < 12288) g_f2[i] = __float2half_rn(f2[i]);
    if (i < 2048)  g_f3[i] = __float2half_rn(f3[i]);
}

static __device__ __forceinline__ unsigned su(const void* p) {
    return (unsigned)__cvta_generic_to_shared(p);
}
static __device__ __forceinline__ void ldm_x4(uint32_t* r, unsigned a) {
    asm volatile("ldmatrix.sync.aligned.m8n8.x4.shared.b16 {%0,%1,%2,%3}, [%4];"
                 : "=r"(r[0]), "=r"(r[1]), "=r"(r[2]), "=r"(r[3]) : "r"(a));
}
static __device__ __forceinline__ void ldm_x2(uint32_t* r, unsigned a) {
    asm volatile("ldmatrix.sync.aligned.m8n8.x2.shared.b16 {%0,%1}, [%2];"
                 : "=r"(r[0]), "=r"(r[1]) : "r"(a));
}
static __device__ __forceinline__ void mma16816(float* c, const uint32_t* a, const uint32_t* b) {
    asm volatile("mma.sync.aligned.m16n8k16.row.col.f32.f16.f16.f32 "
                 "{%0,%1,%2,%3}, {%4,%5,%6,%7}, {%8,%9}, {%0,%1,%2,%3};"
                 : "+f"(c[0]), "+f"(c[1]), "+f"(c[2]), "+f"(c[3])
                 : "r"(a[0]), "r"(a[1]), "r"(a[2]), "r"(a[3]), "r"(b[0]), "r"(b[1]));
}

// fast tanh: exp2 MUFU (~2ulp) rational form
static __device__ __forceinline__ float ft(float v) {
    v = fminf(8.0f, fmaxf(-8.0f, v));
    float e;
    asm("ex2.approx.f32 %0, %1;" : "=f"(e) : "f"(v * 2.8853900817779268f)); // 2*log2(e)
    return __fdividef(e - 1.0f, e + 1.0f);
}

// Warp GEMM: 32 rows x (NF*8) cols, K contraction, fp32 accum.
// A: row-major [rows,K] fp16 smem, LDA halves. W: row-major [cols,K], LDW halves.
// Even NF uses ldmatrix.x4 for B (two n-frags per LDSM).
template <int NF, int K, int LDA, int LDW>
static __device__ __forceinline__ void warp_gemm(const __half* Aw, const __half* Ww,
                                                 float acc[2][NF][4], int lane) {
    unsigned aB = su(Aw + (lane & 15) * LDA + (lane >> 4) * 8);
#pragma unroll
    for (int k0 = 0; k0 < K; k0 += 16) {
        uint32_t a0[4], a1[4];
        ldm_x4(a0, aB + 2 * k0);
        ldm_x4(a1, aB + 32 * LDA + 2 * k0);   // +16 rows (byte addr)
        if constexpr ((NF & 1) == 0) {
            unsigned bB = su(Ww + ((lane & 7) + ((lane & 16) >> 1)) * LDW +
                             ((lane >> 3) & 1) * 8);
#pragma unroll
            for (int ni = 0; ni < NF; ni += 2) {
                uint32_t b[4];
                ldm_x4(b, bB + ni * 16 * LDW + 2 * k0);   // 16 n-rows per x4
                mma16816(acc[0][ni], a0, b);
                mma16816(acc[1][ni], a1, b);
                mma16816(acc[0][ni + 1], a0, b + 2);
                mma16816(acc[1][ni + 1], a1, b + 2);
            }
        } else {
            unsigned bB = su(Ww + (lane & 7) * LDW + ((lane >> 3) & 1) * 8);
#pragma unroll
            for (int ni = 0; ni < NF; ni++) {
                uint32_t b[2];
                ldm_x2(b, bB + ni * 16 * LDW + 2 * k0);
                mma16816(acc[0][ni], a0, b);
                mma16816(acc[1][ni], a1, b);
            }
        }
    }
}

#define ZERO_ACC(A, NFv)                                            \
    _Pragma("unroll") for (int _a = 0; _a < 2; _a++)                \
    _Pragma("unroll") for (int _b = 0; _b < NFv; _b++)              \
    _Pragma("unroll") for (int _c = 0; _c < 4; _c++) A[_a][_b][_c] = 0.f;

__global__ void __launch_bounds__(512, 1)
actor_kernel(const float* __restrict__ gx, const float* __restrict__ gm,
             const float* __restrict__ fc1_b, const float* __restrict__ fc2_b,
             const float* __restrict__ fc3_b, const float* __restrict__ ab_b1,
             const float* __restrict__ ab_b2, const float* __restrict__ ab_b3,
             float* __restrict__ out, int nrows) {
    extern __shared__ __half sm[];
    __half* bufA = sm;                  // [128][264] tanh(xm); later h2
    __half* bufH = sm + 128 * 264;      // raw x (stride SX); then Z (SZ); then h1 (SA)
    __half* bufW = sm + 2 * 128 * 264;  // weights / Z2 / partial-ssq, per OFF_*
    float*  part = (float*)(bufW + OFF_PART);   // [4][128]

    const int tid = threadIdx.x;
    const int lane = tid & 31;
    const int wid = tid >> 5;
    const int wm = wid & 3;        // 4 row-tiles of 32
    const int wn = wid >> 2;       // 4 col-tiles
    const int rin = lane >> 2;
    const int cin = (lane & 3) * 2;
    const int row0 = blockIdx.x * 128;

    // ---- stage: raw x (fp16, bufH) + tanh(x),tanh(m) (bufA); fc weights -> bufW ----
    const float4* x4 = (const float4*)(gx + (size_t)row0 * 128);
    const float4* m4 = (const float4*)(gm + (size_t)row0 * 128);
#pragma unroll
    for (int it = 0; it < 8; it++) {
        int i = tid + it * 512;
        int r = i >> 5, c = i & 31;   // 32 float4 per row
        float4 v = x4[i];
        __half2* xd = (__half2*)(bufH + r * SX + c * 4);
        xd[0] = __floats2half2_rn(v.x, v.y);
        xd[1] = __floats2half2_rn(v.z, v.w);
        __half2* ad = (__half2*)(bufA + r * SA + c * 4);
        ad[0] = __floats2half2_rn(ft(v.x), ft(v.y));
        ad[1] = __floats2half2_rn(ft(v.z), ft(v.w));
        float4 w = m4[i];
        __half2* md = (__half2*)(bufA + r * SA + 128 + c * 4);
        md[0] = __floats2half2_rn(ft(w.x), ft(w.y));
        md[1] = __floats2half2_rn(ft(w.z), ft(w.w));
    }
    {   // fc1 [64][128] -> OFF_F1W (stride SX): 1024 uint4 (16 per row)
        const uint4* s = (const uint4*)g_f1;
#pragma unroll
        for (int it = 0; it < 2; it++) {
            int i = tid + it * 512;
            int r = i >> 4, c = i & 15;
            *(uint4*)(bufW + OFF_F1W + r * SX + c * 8) = s[i];
        }
    }
    {   // fc2 [64][192] -> OFF_F2W (stride SZ): 1536 uint4 (24 per row)
        const uint4* s = (const uint4*)g_f2;
#pragma unroll
        for (int it = 0; it < 3; it++) {
            int i = tid + it * 512;
            int r = i / 24, c = i % 24;
            *(uint4*)(bufW + OFF_F2W + r * SZ + c * 8) = s[i];
        }
    }
    if (tid < 256) {   // fc3 [32][64] -> OFF_F3W (stride SZ2): 256 uint4 (8 per row)
        const uint4* s = (const uint4*)g_f3;
        int r = tid >> 3, c = tid & 7;
        *(uint4*)(bufW + OFF_F3W + r * SZ2 + c * 8) = s[tid];
    }
    __syncthreads();

    // ---- fc1: [128,64] = x @ fc1^T (NF=2), l2norm via reg-ssq ----
    {
        float acc[2][2][4];
        ZERO_ACC(acc, 2)
        warp_gemm<2, 128, SX, SX>(bufH + wm * 32 * SX, bufW + OFF_F1W + wn * 16 * SX,
                                  acc, lane);
        float ssq[4] = {0.f, 0.f, 0.f, 0.f};   // (mi*2+s)
#pragma unroll
        for (int ni = 0; ni < 2; ni++) {
            int col = wn * 16 + ni * 8 + cin;
            float b0 = fc1_b[col], b1 = fc1_b[col + 1];
#pragma unroll
            for (int mi = 0; mi < 2; mi++) {
                acc[mi][ni][0] += b0; acc[mi][ni][1] += b1;
                acc[mi][ni][2] += b0; acc[mi][ni][3] += b1;
                ssq[mi * 2]     += acc[mi][ni][0] * acc[mi][ni][0] + acc[mi][ni][1] * acc[mi][ni][1];
                ssq[mi * 2 + 1] += acc[mi][ni][2] * acc[mi][ni][2] + acc[mi][ni][3] * acc[mi][ni][3];
            }
        }
#pragma unroll
        for (int j = 0; j < 4; j++) {
            ssq[j] += __shfl_xor_sync(0xffffffffu, ssq[j], 1);
            ssq[j] += __shfl_xor_sync(0xffffffffu, ssq[j], 2);
        }
        if ((lane & 3) == 0) {
#pragma unroll
            for (int j = 0; j < 4; j++)
                part[wn * 128 + wm * 32 + j * 8 + rin] = ssq[j];
        }
        __syncthreads();   // also: all fc1 reads of raw-x (bufH) complete
        float inv[4];
#pragma unroll
        for (int j = 0; j < 4; j++) {
            int row = wm * 32 + j * 8 + rin;
            float t = part[row] + part[128 + row] + part[256 + row] + part[384 + row];
            inv[j] = 1.0f / fmaxf(sqrtf(t), 1e-12f);
        }
#pragma unroll
        for (int mi = 0; mi < 2; mi++)
#pragma unroll
            for (int ni = 0; ni < 2; ni++) {
                int row = wm * 32 + mi * 16 + rin;
                int col = wn * 16 + ni * 8 + cin;
                *(__half2*)(bufH + row * SZ + col) = __floats2half2_rn(
                    ft(acc[mi][ni][0] * inv[mi * 2]), ft(acc[mi][ni][1] * inv[mi * 2]));
                *(__half2*)(bufH + (row + 8) * SZ + col) = __floats2half2_rn(
                    ft(acc[mi][ni][2] * inv[mi * 2 + 1]), ft(acc[mi][ni][3] * inv[mi * 2 + 1]));
            }
    }
    // copy tanh(m) -> Z[:,64:192]
#pragma unroll
    for (int it = 0; it < 8; it++) {
        int i = tid + it * 512;
        int r = i >> 5, c = i & 31;
        *(uint2*)(bufH + r * SZ + 64 + c * 4) = *(const uint2*)(bufA + r * SA + 128 + c * 4);
    }
    __syncthreads();

    // ---- fc2: tanh(Z @ fc2^T) -> Z2 (bufW @ OFF_Z2, stride SZ2) ----
    {
        float acc[2][2][4];
        ZERO_ACC(acc, 2)
        warp_gemm<2, 192, SZ, SZ>(bufH + wm * 32 * SZ, bufW + OFF_F2W + wn * 16 * SZ,
                                  acc, lane);
        __syncthreads();   // all fc2 reads of F2W done before Z2 overwrites its head
#pragma unroll
        for (int mi = 0; mi < 2; mi++)
#pragma unroll
            for (int ni = 0; ni < 2; ni++) {
                int row = wm * 32 + mi * 16 + rin;
                int col = wn * 16 + ni * 8 + cin;
                float b0 = fc2_b[col], b1 = fc2_b[col + 1];
                *(__half2*)(bufW + OFF_Z2 + row * SZ2 + col) = __floats2half2_rn(
                    ft(acc[mi][ni][0] + b0), ft(acc[mi][ni][1] + b1));
                *(__half2*)(bufW + OFF_Z2 + (row + 8) * SZ2 + col) = __floats2half2_rn(
                    ft(acc[mi][ni][2] + b0), ft(acc[mi][ni][3] + b1));
            }
    }
    __syncthreads();

    // ---- fc3: [128,32] = Z2 @ fc3^T (NF=1), l2norm -> msg_up out ----
    {
        float acc[2][1][4];
        ZERO_ACC(acc, 1)
        warp_gemm<1, 64, SZ2, SZ2>(bufW + OFF_Z2 + wm * 32 * SZ2,
                                   bufW + OFF_F3W + wn * 8 * SZ2, acc, lane);
        int col = wn * 8 + cin;
        float b0 = fc3_b[col], b1 = fc3_b[col + 1];
        float ssq[4];
#pragma unroll
        for (int mi = 0; mi < 2; mi++) {
            acc[mi][0][0] += b0; acc[mi][0][1] += b1;
            acc[mi][0][2] += b0; acc[mi][0][3] += b1;
            ssq[mi * 2]     = acc[mi][0][0] * acc[mi][0][0] + acc[mi][0][1] * acc[mi][0][1];
            ssq[mi * 2 + 1] = acc[mi][0][2] * acc[mi][0][2] + acc[mi][0][3] * acc[mi][0][3];
        }
#pragma unroll
        for (int j = 0; j < 4; j++) {
            ssq[j] += __shfl_xor_sync(0xffffffffu, ssq[j], 1);
            ssq[j] += __shfl_xor_sync(0xffffffffu, ssq[j], 2);
        }
        if ((lane & 3) == 0) {
#pragma unroll
            for (int j = 0; j < 4; j++)
                part[wn * 128 + wm * 32 + j * 8 + rin] = ssq[j];
        }
        __syncthreads();
#pragma unroll
        for (int mi = 0; mi < 2; mi++)
#pragma unroll
            for (int s = 0; s < 2; s++) {
                int row = wm * 32 + mi * 16 + s * 8 + rin;
                float t = part[row] + part[128 + row] + part[256 + row] + part[384 + row];
                float inv = 1.0f / fmaxf(sqrtf(t), 1e-12f);
                float* od = out + (size_t)(row0 + row) * 32 + col;
                od[0] = acc[mi][0][s * 2] * inv;
                od[1] = acc[mi][0][s * 2 + 1] * inv;
            }
    }

    // ---- action layer 1: h1 = relu(tanh(xm) @ W1^T) -> bufH (stride SA), 2 chunks ----
#pragma unroll 1
    for (int ch = 0; ch < 2; ch++) {
        __syncthreads();
        {   // W1 chunk [128][256] -> bufW (stride SA): 4096 uint4 (32 per row)
            const uint4* s = (const uint4*)(g_w1 + ch * 128 * 256);
#pragma unroll
            for (int it = 0; it < 8; it++) {
                int i = tid + it * 512;
                int r = i >> 5, c = i & 31;
                *(uint4*)(bufW + r * SA + c * 8) = s[i];
            }
        }
        __syncthreads();
        float acc[2][4][4];
        ZERO_ACC(acc, 4)
        warp_gemm<4, 256, SA, SA>(bufA + wm * 32 * SA, bufW + wn * 32 * SA, acc, lane);
#pragma unroll
        for (int mi = 0; mi < 2; mi++)
#pragma unroll
            for (int ni = 0; ni < 4; ni++) {
                int row = wm * 32 + mi * 16 + rin;
                int colg = ch * 128 + wn * 32 + ni * 8 + cin;
                float b0 = ab_b1[colg], b1v = ab_b1[colg + 1];
                *(__half2*)(bufH + row * SA + colg) = __floats2half2_rn(
                    fmaxf(acc[mi][ni][0] + b0, 0.f), fmaxf(acc[mi][ni][1] + b1v, 0.f));
                *(__half2*)(bufH + (row + 8) * SA + colg) = __floats2half2_rn(
                    fmaxf(acc[mi][ni][2] + b0, 0.f), fmaxf(acc[mi][ni][3] + b1v, 0.f));
            }
    }

    // ---- action layer 2: h2 = relu(h1 @ W2^T) -> bufA, 2 chunks ----
#pragma unroll 1
    for (int ch = 0; ch < 2; ch++) {
        __syncthreads();
        {
            const uint4* s = (const uint4*)(g_w2 + ch * 128 * 256);
#pragma unroll
            for (int it = 0; it < 8; it++) {
                int i = tid + it * 512;
                int r = i >> 5, c = i & 31;
                *(uint4*)(bufW + r * SA + c * 8) = s[i];
            }
        }
        __syncthreads();
        float acc[2][4][4];
        ZERO_ACC(acc, 4)
        warp_gemm<4, 256, SA, SA>(bufH + wm * 32 * SA, bufW + wn * 32 * SA, acc, lane);
#pragma unroll
        for (int mi = 0; mi < 2; mi++)
#pragma unroll
            for (int ni = 0; ni < 4; ni++) {
                int row = wm * 32 + mi * 16 + rin;
                int colg = ch * 128 + wn * 32 + ni * 8 + cin;
                float b0 = ab_b2[colg], b1v = ab_b2[colg + 1];
                *(__half2*)(bufA + row * SA + colg) = __floats2half2_rn(
                    fmaxf(acc[mi][ni][0] + b0, 0.f), fmaxf(acc[mi][ni][1] + b1v, 0.f));
                *(__half2*)(bufA + (row + 8) * SA + colg) = __floats2half2_rn(
                    fmaxf(acc[mi][ni][2] + b0, 0.f), fmaxf(acc[mi][ni][3] + b1v, 0.f));
            }
    }
    __syncthreads();

    // ---- final: action = tanh(h2 . w3 + b3) ----
    {
        int r = tid >> 2, q = tid & 3;
        const __half2* hv = (const __half2*)(bufA + r * SA + q * 64);
        const __half2* wv = (const __half2*)(g_w3 + q * 64);
        float s = 0.f;
#pragma unroll
        for (int c = 0; c < 32; c++) {
            float2 a2 = __half22float2(hv[c]);
            float2 w2 = __half22float2(wv[c]);
            s += a2.x * w2.x + a2.y * w2.y;
        }
        s += __shfl_xor_sync(0xffffffffu, s, 1);
        s += __shfl_xor_sync(0xffffffffu, s, 2);
        if (q == 0)
            out[(size_t)nrows * 32 + row0 + r] = ft(s + ab_b3[0]);
    }
}

extern "C" void kernel_launch(void* const* d_in, const int* in_sizes, int n_in,
                              void* d_out, int out_size) {
    const float* x     = (const float*)d_in[0];
    const float* m     = (const float*)d_in[1];
    const float* fc1_w = (const float*)d_in[2];
    const float* fc1_b = (const float*)d_in[3];
    const float* fc2_w = (const float*)d_in[4];
    const float* fc2_b = (const float*)d_in[5];
    const float* fc3_w = (const float*)d_in[6];
    const float* fc3_b = (const float*)d_in[7];
    const float* ab_w1 = (const float*)d_in[8];
    const float* ab_b1 = (const float*)d_in[9];
    const float* ab_w2 = (const float*)d_in[10];
    const float* ab_b2 = (const float*)d_in[11];
    const float* ab_w3 = (const float*)d_in[12];
    const float* ab_b3 = (const float*)d_in[13];
    float* out = (float*)d_out;
    int nrows = in_sizes[0] / 128;

    static bool attr_done = false;
    if (!attr_done) {
        cudaFuncSetAttribute(actor_kernel,
                             cudaFuncAttributeMaxDynamicSharedMemorySize, SMEM_BYTES);
        attr_done = true;
    }

    cvtw_kernel<<<256, 256>>>(ab_w1, ab_w2, ab_w3, fc1_w, fc2_w, fc3_w);
    actor_kernel<<<nrows / 128, 512, SMEM_BYTES>>>(
        x, m, fc1_b, fc2_b, fc3_b, ab_b1, ab_b2, ab_b3, out, nrows);
}

// round 10
// speedup vs baseline: 1.3231x; 1.1237x over previous
#include <cuda_runtime.h>
#include <cuda_fp16.h>
#include <cstdint>
#include <cstddef>

// ---------------------------------------------------------------------------
// ActorUpAction v4b: fp16 mma.sync, 512 threads. Big action layers use 64x32
// warp tiles over the full 256-col layer with K split in 2 register-accumulated
// halves; weights staged via cp.async; final dot computed from registers.
// (v4 + fix: second B-ldmatrix row offset 32*SW bytes, was 16*SW)
//   action: tanh([x,m]) -> 256x256 relu -> 256x256 relu -> dot(256) -> tanh
//   msg:    l2n(x@fc1[64x128]) -> tanh([hx,m]) -> tanh(fc2[64x192]) -> l2n(fc3[32x64])
// Output: msg_up [B,32] fp32 then action [B] fp32.
// ---------------------------------------------------------------------------

#define SA 264   // halves stride, 256-wide activation tiles (K=256+8)
#define SX 136   // halves stride, raw-x / fc1 weights (K=128+8)
#define SZ 200   // halves stride, Z / fc2 weights (K=192+8)
#define SZ2 72   // halves stride, Z2 / fc3 weights (K=64+8)
#define SW 136   // halves stride, big-layer weight K-half buffer (128+8)

// smem byte offsets
#define OFF_A    0         // tanh([x,m]) 128 x SA fp16 (67584 B)
#define OFF_H    67584     // raw-x (SX) / Z (SZ) / h1 (SA)  (67584 B)
#define OFF_W    135168    // weight buffer 256 x SW fp16 (69632 B)
#define OFF_PART 204800    // 1024 floats (4096 B)
#define SMEM_BYTES 208896

// msg-phase overlays inside W region
#define OFF_F1   OFF_W
#define OFF_F2   (OFF_W + 20480)
#define OFF_F3   (OFF_W + 46080)
#define OFF_Z2   OFF_W     // 128 x SZ2 x 2 = 18432 <= 20480 (f1 dead by then)

// big-layer weights in global: fp16, [half h][col n][k] = h*32768 + n*128 + k
__device__ __half g_w1[65536];
__device__ __half g_w2[65536];
__device__ __half g_f1[64*128];
__device__ __half g_f2[64*192];
__device__ __half g_f3[32*64];

__global__ void cvtw_kernel(const float* __restrict__ w1, const float* __restrict__ w2,
                            const float* __restrict__ f1, const float* __restrict__ f2,
                            const float* __restrict__ f3) {
    int i = blockIdx.x * blockDim.x + threadIdx.x;   // 65536
    int n = i >> 8, K = i & 255;
    int dst = (K >> 7) * 32768 + n * 128 + (K & 127);
    g_w1[dst] = __float2half_rn(w1[i]);
    g_w2[dst] = __float2half_rn(w2[i]);
    if (i < 8192)  g_f1[i] = __float2half_rn(f1[i]);
    if (i < 12288) g_f2[i] = __float2half_rn(f2[i]);
    if (i < 2048)  g_f3[i] = __float2half_rn(f3[i]);
}

static __device__ __forceinline__ unsigned su(const void* p) {
    return (unsigned)__cvta_generic_to_shared(p);
}
static __device__ __forceinline__ void ldm_x4(uint32_t* r, unsigned a) {
    asm volatile("ldmatrix.sync.aligned.m8n8.x4.shared.b16 {%0,%1,%2,%3}, [%4];"
                 : "=r"(r[0]), "=r"(r[1]), "=r"(r[2]), "=r"(r[3]) : "r"(a));
}
static __device__ __forceinline__ void ldm_x2(uint32_t* r, unsigned a) {
    asm volatile("ldmatrix.sync.aligned.m8n8.x2.shared.b16 {%0,%1}, [%2];"
                 : "=r"(r[0]), "=r"(r[1]) : "r"(a));
}
static __device__ __forceinline__ void mma16816(float* c, const uint32_t* a, const uint32_t* b) {
    asm volatile("mma.sync.aligned.m16n8k16.row.col.f32.f16.f16.f32 "
                 "{%0,%1,%2,%3}, {%4,%5,%6,%7}, {%8,%9}, {%0,%1,%2,%3};"
                 : "+f"(c[0]), "+f"(c[1]), "+f"(c[2]), "+f"(c[3])
                 : "r"(a[0]), "r"(a[1]), "r"(a[2]), "r"(a[3]), "r"(b[0]), "r"(b[1]));
}
static __device__ __forceinline__ float ft(float v) {
    v = fminf(8.0f, fmaxf(-8.0f, v));
    float e;
    asm("ex2.approx.f32 %0, %1;" : "=f"(e) : "f"(v * 2.8853900817779268f));
    return __fdividef(e - 1.0f, e + 1.0f);
}
static __device__ __forceinline__ void cpa16(uint32_t dst, const void* src) {
    asm volatile("cp.async.cg.shared.global [%0], [%1], 16;" :: "r"(dst), "l"(src) : "memory");
}
#define CPA_COMMIT() asm volatile("cp.async.commit_group;" ::: "memory")
#define CPA_WAIT0()  asm volatile("cp.async.wait_group 0;" ::: "memory")

// Msg-branch warp GEMM (proven v2b): 32 rows x NF*8 cols, fp32 accum.
template <int NF, int K, int LDA, int LDW>
static __device__ __forceinline__ void warp_gemm(const __half* Aw, const __half* Ww,
                                                 float acc[2][NF][4], int lane) {
    unsigned aB = su(Aw + (lane & 15) * LDA + (lane >> 4) * 8);
#pragma unroll
    for (int k0 = 0; k0 < K; k0 += 16) {
        uint32_t a0[4], a1[4];
        ldm_x4(a0, aB + 2 * k0);
        ldm_x4(a1, aB + 32 * LDA + 2 * k0);
        if constexpr ((NF & 1) == 0) {
            unsigned bB = su(Ww + ((lane & 7) + ((lane & 16) >> 1)) * LDW +
                             ((lane >> 3) & 1) * 8);
#pragma unroll
            for (int ni = 0; ni < NF; ni += 2) {
                uint32_t b[4];
                ldm_x4(b, bB + ni * 16 * LDW + 2 * k0);
                mma16816(acc[0][ni], a0, b);
                mma16816(acc[1][ni], a1, b);
                mma16816(acc[0][ni + 1], a0, b + 2);
                mma16816(acc[1][ni + 1], a1, b + 2);
            }
        } else {
            unsigned bB = su(Ww + (lane & 7) * LDW + ((lane >> 3) & 1) * 8);
#pragma unroll
            for (int ni = 0; ni < NF; ni++) {
                uint32_t b[2];
                ldm_x2(b, bB + ni * 16 * LDW + 2 * k0);
                mma16816(acc[0][ni], a0, b);
                mma16816(acc[1][ni], a1, b);
            }
        }
    }
}

// Action-branch warp GEMM: 64 rows x 32 cols, one K=128 half, accumulate.
// A: [rows, 256] stride SA (pass pointer pre-offset by k-half). W: [32 cols, SW].
static __device__ __forceinline__ void gemm64(const __half* Aw, const __half* Ww,
                                              float acc[4][4][4], int lane) {
    unsigned aB = su(Aw + (lane & 15) * SA + (lane >> 4) * 8);
    unsigned bB = su(Ww + ((lane & 7) + ((lane & 16) >> 1)) * SW + ((lane >> 3) & 1) * 8);
#pragma unroll
    for (int k0 = 0; k0 < 128; k0 += 16) {
        uint32_t a[4][4];
#pragma unroll
        for (int mf = 0; mf < 4; mf++) ldm_x4(a[mf], aB + mf * 32 * SA + 2 * k0);
        uint32_t b[8];
        ldm_x4(b, bB + 2 * k0);
        ldm_x4(b + 4, bB + 32 * SW + 2 * k0);   // cols 16-31: 16 rows = 32*SW BYTES
#pragma unroll
        for (int mf = 0; mf < 4; mf++)
#pragma unroll
            for (int nf = 0; nf < 4; nf++)
                mma16816(acc[mf][nf], a[mf], b + nf * 2);
    }
}

// cp.async one 64KB weight K-half into OFF_W ([256 cols][SW halves])
static __device__ __forceinline__ void loadW(char* smem, const __half* gsrc, int tid) {
#pragma unroll
    for (int it = 0; it < 8; it++) {
        int i = tid + it * 512;
        int n = i >> 4, c = i & 15;
        cpa16(su(smem + OFF_W + n * (SW * 2) + c * 16), gsrc + n * 128 + c * 8);
    }
}

#define ZERO_ACC2(A)                                                \
    _Pragma("unroll") for (int _a = 0; _a < 2; _a++)                \
    _Pragma("unroll") for (int _b = 0; _b < 2; _b++)                \
    _Pragma("unroll") for (int _c = 0; _c < 4; _c++) A[_a][_b][_c] = 0.f;

__global__ void __launch_bounds__(512, 1)
actor_kernel(const float* __restrict__ gx, const float* __restrict__ gm,
             const float* __restrict__ fc1_b, const float* __restrict__ fc2_b,
             const float* __restrict__ fc3_b, const float* __restrict__ ab_b1,
             const float* __restrict__ ab_b2, const float* __restrict__ ab_w3,
             const float* __restrict__ ab_b3, float* __restrict__ out, int nrows) {
    extern __shared__ char smem[];
    __half* bufA = (__half*)(smem + OFF_A);
    __half* bufH = (__half*)(smem + OFF_H);
    float* part = (float*)(smem + OFF_PART);

    const int tid = threadIdx.x;
    const int lane = tid & 31;
    const int wid = tid >> 5;
    const int wm = wid & 3;        // msg: 4 row-tiles of 32
    const int wn = wid >> 2;       // msg: 4 col-tiles
    const int wm2 = wid & 1;       // action: 2 row-tiles of 64
    const int wn2 = wid >> 1;      // action: 8 col-tiles of 32
    const int rin = lane >> 2;
    const int cin = (lane & 3) * 2;
    const int row0 = blockIdx.x * 128;

    // ---- msg fc weights via cp.async (into W overlays) ----
    {
        const __half* f1 = g_f1;
#pragma unroll
        for (int it = 0; it < 2; it++) {
            int i = tid + it * 512;
            int r = i >> 4, c = i & 15;
            cpa16(su(smem + OFF_F1 + r * (SX * 2) + c * 16), f1 + r * 128 + c * 8);
        }
        const __half* f2 = g_f2;
#pragma unroll
        for (int it = 0; it < 3; it++) {
            int i = tid + it * 512;
            int r = i / 24, c = i % 24;
            cpa16(su(smem + OFF_F2 + r * (SZ * 2) + c * 16), f2 + r * 192 + c * 8);
        }
        if (tid < 256) {
            int r = tid >> 3, c = tid & 7;
            cpa16(su(smem + OFF_F3 + r * (SZ2 * 2) + c * 16), g_f3 + r * 64 + c * 8);
        }
        CPA_COMMIT();
    }

    // ---- stage inputs: raw x fp16 -> bufH (SX); tanh(x),tanh(m) -> bufA (SA) ----
    const float4* x4 = (const float4*)(gx + (size_t)row0 * 128);
    const float4* m4 = (const float4*)(gm + (size_t)row0 * 128);
#pragma unroll
    for (int it = 0; it < 8; it++) {
        int i = tid + it * 512;
        int r = i >> 5, c = i & 31;
        float4 v = x4[i];
        __half2* xd = (__half2*)(bufH + r * SX + c * 4);
        xd[0] = __floats2half2_rn(v.x, v.y);
        xd[1] = __floats2half2_rn(v.z, v.w);
        __half2* ad = (__half2*)(bufA + r * SA + c * 4);
        ad[0] = __floats2half2_rn(ft(v.x), ft(v.y));
        ad[1] = __floats2half2_rn(ft(v.z), ft(v.w));
        float4 w = m4[i];
        __half2* md = (__half2*)(bufA + r * SA + 128 + c * 4);
        md[0] = __floats2half2_rn(ft(w.x), ft(w.y));
        md[1] = __floats2half2_rn(ft(w.z), ft(w.w));
    }
    CPA_WAIT0();
    __syncthreads();

    // ================= message branch =================
    {   // fc1: [128,64] = rawx @ f1^T, l2norm
        float acc[2][2][4];
        ZERO_ACC2(acc)
        warp_gemm<2, 128, SX, SX>(bufH + wm * 32 * SX,
                                  (__half*)(smem + OFF_F1) + wn * 16 * SX, acc, lane);
        float ssq[4] = {0.f, 0.f, 0.f, 0.f};
#pragma unroll
        for (int ni = 0; ni < 2; ni++) {
            int col = wn * 16 + ni * 8 + cin;
            float b0 = fc1_b[col], b1 = fc1_b[col + 1];
#pragma unroll
            for (int mi = 0; mi < 2; mi++) {
                acc[mi][ni][0] += b0; acc[mi][ni][1] += b1;
                acc[mi][ni][2] += b0; acc[mi][ni][3] += b1;
                ssq[mi * 2]     += acc[mi][ni][0] * acc[mi][ni][0] + acc[mi][ni][1] * acc[mi][ni][1];
                ssq[mi * 2 + 1] += acc[mi][ni][2] * acc[mi][ni][2] + acc[mi][ni][3] * acc[mi][ni][3];
            }
        }
#pragma unroll
        for (int j = 0; j < 4; j++) {
            ssq[j] += __shfl_xor_sync(0xffffffffu, ssq[j], 1);
            ssq[j] += __shfl_xor_sync(0xffffffffu, ssq[j], 2);
        }
        if ((lane & 3) == 0) {
#pragma unroll
            for (int j = 0; j < 4; j++)
                part[wn * 128 + wm * 32 + j * 8 + rin] = ssq[j];
        }
        __syncthreads();   // fc1 reads of rawx done; part ready
        float inv[4];
#pragma unroll
        for (int j = 0; j < 4; j++) {
            int row = wm * 32 + j * 8 + rin;
            float t = part[row] + part[128 + row] + part[256 + row] + part[384 + row];
            inv[j] = 1.0f / fmaxf(sqrtf(t), 1e-12f);
        }
#pragma unroll
        for (int mi = 0; mi < 2; mi++)
#pragma unroll
            for (int ni = 0; ni < 2; ni++) {
                int row = wm * 32 + mi * 16 + rin;
                int col = wn * 16 + ni * 8 + cin;
                *(__half2*)(bufH + row * SZ + col) = __floats2half2_rn(
                    ft(acc[mi][ni][0] * inv[mi * 2]), ft(acc[mi][ni][1] * inv[mi * 2]));
                *(__half2*)(bufH + (row + 8) * SZ + col) = __floats2half2_rn(
                    ft(acc[mi][ni][2] * inv[mi * 2 + 1]), ft(acc[mi][ni][3] * inv[mi * 2 + 1]));
            }
    }
    // copy tanh(m) -> Z[:,64:192]
#pragma unroll
    for (int it = 0; it < 8; it++) {
        int i = tid + it * 512;
        int r = i >> 5, c = i & 31;
        *(uint2*)(bufH + r * SZ + 64 + c * 4) = *(const uint2*)(bufA + r * SA + 128 + c * 4);
    }
    __syncthreads();

    {   // fc2: tanh(Z @ f2^T) -> Z2
        float acc[2][2][4];
        ZERO_ACC2(acc)
        warp_gemm<2, 192, SZ, SZ>(bufH + wm * 32 * SZ,
                                  (__half*)(smem + OFF_F2) + wn * 16 * SZ, acc, lane);
        __syncthreads();   // all fc2 reads done before Z2 overwrites f1 region
#pragma unroll
        for (int mi = 0; mi < 2; mi++)
#pragma unroll
            for (int ni = 0; ni < 2; ni++) {
                int row = wm * 32 + mi * 16 + rin;
                int col = wn * 16 + ni * 8 + cin;
                float b0 = fc2_b[col], b1 = fc2_b[col + 1];
                *(__half2*)((__half*)(smem + OFF_Z2) + row * SZ2 + col) =
                    __floats2half2_rn(ft(acc[mi][ni][0] + b0), ft(acc[mi][ni][1] + b1));
                *(__half2*)((__half*)(smem + OFF_Z2) + (row + 8) * SZ2 + col) =
                    __floats2half2_rn(ft(acc[mi][ni][2] + b0), ft(acc[mi][ni][3] + b1));
            }
    }
    __syncthreads();

    {   // fc3: [128,32] = Z2 @ f3^T, l2norm -> msg out
        float acc[2][1][4];
#pragma unroll
        for (int _a = 0; _a < 2; _a++)
#pragma unroll
            for (int _c = 0; _c < 4; _c++) acc[_a][0][_c] = 0.f;
        warp_gemm<1, 64, SZ2, SZ2>((__half*)(smem + OFF_Z2) + wm * 32 * SZ2,
                                   (__half*)(smem + OFF_F3) + wn * 8 * SZ2, acc, lane);
        int col = wn * 8 + cin;
        float b0 = fc3_b[col], b1 = fc3_b[col + 1];
        float ssq[4];
#pragma unroll
        for (int mi = 0; mi < 2; mi++) {
            acc[mi][0][0] += b0; acc[mi][0][1] += b1;
            acc[mi][0][2] += b0; acc[mi][0][3] += b1;
            ssq[mi * 2]     = acc[mi][0][0] * acc[mi][0][0] + acc[mi][0][1] * acc[mi][0][1];
            ssq[mi * 2 + 1] = acc[mi][0][2] * acc[mi][0][2] + acc[mi][0][3] * acc[mi][0][3];
        }
#pragma unroll
        for (int j = 0; j < 4; j++) {
            ssq[j] += __shfl_xor_sync(0xffffffffu, ssq[j], 1);
            ssq[j] += __shfl_xor_sync(0xffffffffu, ssq[j], 2);
        }
        if ((lane & 3) == 0) {
#pragma unroll
            for (int j = 0; j < 4; j++)
                part[wn * 128 + wm * 32 + j * 8 + rin] = ssq[j];
        }
        __syncthreads();
#pragma unroll
        for (int mi = 0; mi < 2; mi++)
#pragma unroll
            for (int s = 0; s < 2; s++) {
                int row = wm * 32 + mi * 16 + s * 8 + rin;
                float t = part[row] + part[128 + row] + part[256 + row] + part[384 + row];
                float inv = 1.0f / fmaxf(sqrtf(t), 1e-12f);
                float* od = out + (size_t)(row0 + row) * 32 + col;
                od[0] = acc[mi][0][s * 2] * inv;
                od[1] = acc[mi][0][s * 2 + 1] * inv;
            }
    }
    __syncthreads();   // msg done; W and H regions free

    // ================= action branch =================
    float acc[4][4][4];
#pragma unroll
    for (int a = 0; a < 4; a++)
#pragma unroll
        for (int b = 0; b < 4; b++)
#pragma unroll
            for (int c = 0; c < 4; c++) acc[a][b][c] = 0.f;

    const __half* Wsm = (const __half*)(smem + OFF_W) + wn2 * 32 * SW;

    // --- layer 1: acc = tanh(xm) @ W1^T (+bias,relu) -> h1 in bufH ---
    loadW(smem, g_w1, tid);            CPA_COMMIT(); CPA_WAIT0(); __syncthreads();
    gemm64(bufA + wm2 * 64 * SA, Wsm, acc, lane);
    __syncthreads();                   // weight reads done
    loadW(smem, g_w1 + 32768, tid);    CPA_COMMIT(); CPA_WAIT0(); __syncthreads();
    gemm64(bufA + wm2 * 64 * SA + 128, Wsm, acc, lane);
    __syncthreads();                   // weight reads done
    loadW(smem, g_w2, tid);            CPA_COMMIT();   // prefetch L2-h0 during epilogue
#pragma unroll
    for (int mf = 0; mf < 4; mf++)
#pragma unroll
        for (int nf = 0; nf < 4; nf++) {
            int row = wm2 * 64 + mf * 16 + rin;
            int col = wn2 * 32 + nf * 8 + cin;
            float b0 = ab_b1[col], b1v = ab_b1[col + 1];
            *(__half2*)(bufH + row * SA + col) = __floats2half2_rn(
                fmaxf(acc[mf][nf][0] + b0, 0.f), fmaxf(acc[mf][nf][1] + b1v, 0.f));
            *(__half2*)(bufH + (row + 8) * SA + col) = __floats2half2_rn(
                fmaxf(acc[mf][nf][2] + b0, 0.f), fmaxf(acc[mf][nf][3] + b1v, 0.f));
        }
    CPA_WAIT0();
    __syncthreads();                   // h1 visible + W2-h0 ready

    // --- layer 2: acc = h1 @ W2^T, stays in registers ---
#pragma unroll
    for (int a = 0; a < 4; a++)
#pragma unroll
        for (int b = 0; b < 4; b++)
#pragma unroll
            for (int c = 0; c < 4; c++) acc[a][b][c] = 0.f;
    gemm64(bufH + wm2 * 64 * SA, Wsm, acc, lane);
    __syncthreads();
    loadW(smem, g_w2 + 32768, tid);    CPA_COMMIT(); CPA_WAIT0(); __syncthreads();
    gemm64(bufH + wm2 * 64 * SA + 128, Wsm, acc, lane);

    // --- final: action = tanh( relu(acc + b2) . w3 + b3 ), from registers ---
    {
        float s[8];
#pragma unroll
        for (int j = 0; j < 8; j++) s[j] = 0.f;
#pragma unroll
        for (int nf = 0; nf < 4; nf++) {
            int col = wn2 * 32 + nf * 8 + cin;
            float b20 = ab_b2[col], b21 = ab_b2[col + 1];
            float w30 = ab_w3[col], w31 = ab_w3[col + 1];
#pragma unroll
            for (int mf = 0; mf < 4; mf++) {
                s[mf * 2]     += fmaxf(acc[mf][nf][0] + b20, 0.f) * w30 +
                                 fmaxf(acc[mf][nf][1] + b21, 0.f) * w31;
                s[mf * 2 + 1] += fmaxf(acc[mf][nf][2] + b20, 0.f) * w30 +
                                 fmaxf(acc[mf][nf][3] + b21, 0.f) * w31;
            }
        }
#pragma unroll
        for (int j = 0; j < 8; j++) {
            s[j] += __shfl_xor_sync(0xffffffffu, s[j], 1);
            s[j] += __shfl_xor_sync(0xffffffffu, s[j], 2);
        }
        __syncthreads();   // part free (msg usage done)
        if ((lane & 3) == 0) {
#pragma unroll
            for (int mf = 0; mf < 4; mf++)
#pragma unroll
                for (int rh = 0; rh < 2; rh++)
                    part[wn2 * 128 + wm2 * 64 + mf * 16 + rh * 8 + rin] = s[mf * 2 + rh];
        }
    }
    __syncthreads();
    if (tid < 128) {
        float s = 0.f;
#pragma unroll
        for (int q = 0; q < 8; q++) s += part[q * 128 + tid];
        out[(size_t)nrows * 32 + row0 + tid] = ft(s + ab_b3[0]);
    }
}

extern "C" void kernel_launch(void* const* d_in, const int* in_sizes, int n_in,
                              void* d_out, int out_size) {
    const float* x     = (const float*)d_in[0];
    const float* m     = (const float*)d_in[1];
    const float* fc1_w = (const float*)d_in[2];
    const float* fc1_b = (const float*)d_in[3];
    const float* fc2_w = (const float*)d_in[4];
    const float* fc2_b = (const float*)d_in[5];
    const float* fc3_w = (const float*)d_in[6];
    const float* fc3_b = (const float*)d_in[7];
    const float* ab_w1 = (const float*)d_in[8];
    const float* ab_b1 = (const float*)d_in[9];
    const float* ab_w2 = (const float*)d_in[10];
    const float* ab_b2 = (const float*)d_in[11];
    const float* ab_w3 = (const float*)d_in[12];
    const float* ab_b3 = (const float*)d_in[13];
    float* out = (float*)d_out;
    int nrows = in_sizes[0] / 128;

    static bool attr_done = false;
    if (!attr_done) {
        cudaFuncSetAttribute(actor_kernel,
                             cudaFuncAttributeMaxDynamicSharedMemorySize, SMEM_BYTES);
        attr_done = true;
    }

    cvtw_kernel<<<256, 256>>>(ab_w1, ab_w2, fc1_w, fc2_w, fc3_w);
    actor_kernel<<<nrows / 128, 512, SMEM_BYTES>>>(
        x, m, fc1_b, fc2_b, fc3_b, ab_b1, ab_b2, ab_w3, ab_b3, out, nrows);
}